// round 7
// baseline (speedup 1.0000x reference)
#include <cuda_runtime.h>
#include <cuda_fp16.h>
#include <cstdint>
#include <math.h>

#define B_ 1024
#define D_ 512
#define K_ 256
#define J_ 1024   // reduction length: [x^2 | x]

// ---------------- scratch (no allocations allowed) ----------------
__device__ __half g_A[B_ * J_];   // [b][j]: j<512 -> x^2, j>=512 -> x
__device__ __half g_Bv[K_ * J_];  // [k][j]: j<512 -> 0.5*s2, j>=512 -> -m*s2
__device__ float g_C[K_];         // 0.5 * sum_d m^2 s2

__device__ __forceinline__ uint32_t smem_u32(const void* p) {
    uint32_t a;
    asm("{ .reg .u64 t; cvta.to.shared.u64 t, %1; cvt.u32.u64 %0, t; }" : "=r"(a) : "l"(p));
    return a;
}
__device__ __forceinline__ void cpasync16(uint32_t dst, const void* src) {
    asm volatile("cp.async.cg.shared.global [%0], [%1], 16;\n" :: "r"(dst), "l"(src) : "memory");
}
template <int N> __device__ __forceinline__ void cp_wait() {
    asm volatile("cp.async.wait_group %0;\n" :: "n"(N) : "memory");
}

// ---------------------------------------------------------------------------
// Fused prep (unchanged from R6).
// ---------------------------------------------------------------------------
#define NB_U 256
#define NB_V 32
#define NB_Z 32

__global__ __launch_bounds__(256) void prep_kernel(const float* __restrict__ x,
                                                   const float* __restrict__ means,
                                                   const float* __restrict__ rho,
                                                   float* __restrict__ out) {
    const int blk = blockIdx.x;
    const int tid = threadIdx.x;
    if (blk < NB_U) {
        #pragma unroll
        for (int i = 0; i < 2; i++) {
            const int idx = blk * 256 + tid + i * 65536;  // float4 index over B*D/4
            const int b = idx >> 7;                       // 128 float4 per x row
            const int d = (idx & 127) * 4;
            float4 xv = ((const float4*)x)[idx];
            size_t base = (size_t)b * J_ + d;
            *(__half2*)&g_A[base]          = __floats2half2_rn(xv.x * xv.x, xv.y * xv.y);
            *(__half2*)&g_A[base + 2]      = __floats2half2_rn(xv.z * xv.z, xv.w * xv.w);
            *(__half2*)&g_A[base + D_]     = __floats2half2_rn(xv.x, xv.y);
            *(__half2*)&g_A[base + D_ + 2] = __floats2half2_rn(xv.z, xv.w);
        }
    } else if (blk < NB_U + NB_V) {
        const int wid = tid >> 5, lane = tid & 31;
        const int k = (blk - NB_U) * 8 + wid;      // 32 blocks x 8 warps = 256 k's
        const float4* mrow = (const float4*)(means + (size_t)k * D_);
        const float4* rrow = (const float4*)(rho   + (size_t)k * D_);
        float csum = 0.0f;
        #pragma unroll
        for (int i = 0; i < 4; i++) {
            int d4 = lane + i * 32;                // float4 index 0..127
            float4 m = mrow[d4];
            float4 r = rrow[d4];
            float mm[4] = {m.x, m.y, m.z, m.w};
            float rr[4] = {r.x, r.y, r.z, r.w};
            float v0[4], v1[4];
            #pragma unroll
            for (int c = 0; c < 4; c++) {
                float s  = __logf(1.0f + __expf(rr[c]));   // softplus (fast)
                float s2 = s * s;
                v0[c] = 0.5f * s2;
                v1[c] = -mm[c] * s2;
                csum += 0.5f * mm[c] * mm[c] * s2;
            }
            size_t base = (size_t)k * J_ + d4 * 4;
            *(__half2*)&g_Bv[base]          = __floats2half2_rn(v0[0], v0[1]);
            *(__half2*)&g_Bv[base + 2]      = __floats2half2_rn(v0[2], v0[3]);
            *(__half2*)&g_Bv[base + D_]     = __floats2half2_rn(v1[0], v1[1]);
            *(__half2*)&g_Bv[base + D_ + 2] = __floats2half2_rn(v1[2], v1[3]);
        }
        #pragma unroll
        for (int off = 16; off > 0; off >>= 1)
            csum += __shfl_xor_sync(0xFFFFFFFFu, csum, off);
        if (lane == 0) g_C[k] = csum;
    } else {
        float4* o4 = (float4*)out;
        const int base = (blk - NB_U - NB_V) * 256 + tid;   // 8192 per pass
        const float4 z = make_float4(0.f, 0.f, 0.f, 0.f);
        #pragma unroll
        for (int i = 0; i < 8; i++) o4[base + i * 8192] = z;
    }
}

// ---------------------------------------------------------------------------
// HMMA GEMM (fp16), split-K=4: out += U*V^T (+ C from z==0 only).
// CTA tile 64x64, KC=128, ring-of-2 fully preloaded. Grid (16,4,4)=256 CTAs,
// 2 CTAs/SM. Register double-buffered fragments hide LDS latency.
// Epilogue via red.global.add.v2.f32 (no return, vectorized).
// ---------------------------------------------------------------------------
#define BM 64
#define BN 64
#define KC 128
#define KSPLIT 4
#define KPER (J_ / KSPLIT)        // 256
#define NSTAGE (KPER / KC)        // 2
#define ROWB 272                  // 128 fp16 (256B) + 16B pad -> conflict-free
#define OFF_A 0
#define OFF_B (BM * ROWB)                     // 17408
#define STAGE_BYTES ((BM + BN) * ROWB)        // 34816

__device__ __forceinline__ void ldm4(uint32_t* f, uint32_t addr) {
    asm volatile("ldmatrix.sync.aligned.m8n8.x4.shared.b16 {%0,%1,%2,%3}, [%4];"
                 : "=r"(f[0]), "=r"(f[1]), "=r"(f[2]), "=r"(f[3]) : "r"(addr));
}
__device__ __forceinline__ void mma16816(float* c, const uint32_t* a, uint32_t b0, uint32_t b1) {
    asm volatile("mma.sync.aligned.m16n8k16.row.col.f32.f16.f16.f32 "
                 "{%0,%1,%2,%3}, {%4,%5,%6,%7}, {%8,%9}, {%0,%1,%2,%3};"
                 : "+f"(c[0]), "+f"(c[1]), "+f"(c[2]), "+f"(c[3])
                 : "r"(a[0]), "r"(a[1]), "r"(a[2]), "r"(a[3]), "r"(b0), "r"(b1));
}
__device__ __forceinline__ void red_v2(float* p, float a, float b) {
    asm volatile("red.global.add.v2.f32 [%0], {%1, %2};" :: "l"(p), "f"(a), "f"(b) : "memory");
}

__device__ __forceinline__ void load_stage(uint32_t sb, int m0, int n0, int kelem, int tid) {
    const char* baseA = (const char*)g_A;
    const char* baseB = (const char*)g_Bv;
    const size_t kb = (size_t)kelem * 2;   // byte offset within a 2048B row
    #pragma unroll
    for (int i = 0; i < 4; i++) {          // A: 64 rows x 16 chunks = 1024 positions
        int idx = tid + i * 256;
        int r = idx >> 4, c = idx & 15;
        uint32_t so = (uint32_t)(r * ROWB + c * 16);
        cpasync16(sb + OFF_A + so, baseA + (size_t)(m0 + r) * 2048 + kb + c * 16);
    }
    #pragma unroll
    for (int i = 0; i < 4; i++) {          // B: 64 rows x 16 chunks = 1024 positions
        int idx = tid + i * 256;
        int r = idx >> 4, c = idx & 15;
        uint32_t so = (uint32_t)(r * ROWB + c * 16);
        cpasync16(sb + OFF_B + so, baseB + (size_t)(n0 + r) * 2048 + kb + c * 16);
    }
    asm volatile("cp.async.commit_group;\n" ::: "memory");
}

__global__ __launch_bounds__(256, 2) void gemm_kernel(float* __restrict__ out) {
    extern __shared__ char dyn[];
    __shared__ float Cs[BN];

    const int tid = threadIdx.x;
    const int wid = tid >> 5, lane = tid & 31;
    const int m0 = blockIdx.x * BM;
    const int n0 = blockIdx.y * BN;
    const int kbase = blockIdx.z * KPER;
    const int mw = (wid & 3) * 16;         // warp M offset
    const int nw = (wid >> 2) * 32;        // warp N offset

    const uint32_t sbase = smem_u32(dyn);

    // Prologue: issue BOTH stages' loads at once (max MLP, one L2 latency).
    #pragma unroll
    for (int s = 0; s < NSTAGE; s++)
        load_stage(sbase + s * STAGE_BYTES, m0, n0, kbase + s * KC, tid);

    if (tid < BN) Cs[tid] = g_C[n0 + tid];

    float acc[16];
    #pragma unroll
    for (int i = 0; i < 16; i++) acc[i] = 0.f;

    const uint32_t aRow  = (uint32_t)((mw + (lane & 15)) * ROWB);
    const uint32_t aCol  = (uint32_t)((lane >> 4) * 16);
    const uint32_t bRow0 = (uint32_t)((nw + (lane & 7) + ((lane >> 4) << 3)) * ROWB);
    const uint32_t bRow1 = bRow0 + 16 * ROWB;
    const uint32_t bCol  = (uint32_t)((((lane >> 3) & 1) << 3) * 2);

    #pragma unroll
    for (int s = 0; s < NSTAGE; s++) {
        if (s == 0) cp_wait<1>();
        else        cp_wait<0>();
        __syncthreads();

        const uint32_t sb = sbase + s * STAGE_BYTES;
        const uint32_t aB = sb + OFF_A + aRow + aCol;
        const uint32_t b0B = sb + OFF_B + bRow0 + bCol;
        const uint32_t b1B = sb + OFF_B + bRow1 + bCol;

        // Register double-buffered fragments: prefetch kk+1 while MMA'ing kk.
        uint32_t aF[2][4], bL[2][4], bH[2][4];
        ldm4(aF[0], aB);
        ldm4(bL[0], b0B);
        ldm4(bH[0], b1B);
        #pragma unroll
        for (int kk = 0; kk < KC / 16; kk++) {
            const int cur = kk & 1, nxt = cur ^ 1;
            if (kk + 1 < KC / 16) {
                const uint32_t kbb = (uint32_t)((kk + 1) * 32);
                ldm4(aF[nxt], aB + kbb);
                ldm4(bL[nxt], b0B + kbb);
                ldm4(bH[nxt], b1B + kbb);
            }
            mma16816(acc + 0,  aF[cur], bL[cur][0], bL[cur][1]);
            mma16816(acc + 4,  aF[cur], bL[cur][2], bL[cur][3]);
            mma16816(acc + 8,  aF[cur], bH[cur][0], bH[cur][1]);
            mma16816(acc + 12, aF[cur], bH[cur][2], bH[cur][3]);
        }
        // no trailing barrier: buffers never reused
    }

    // Epilogue: vectorized no-return reductions into out (zeroed by prep).
    // Only the z==0 split adds the bias C.
    const int row = lane >> 2;
    const int col = (lane & 3) * 2;
    const int gr0 = m0 + mw + row;
    const bool addc = (blockIdx.z == 0);
    #pragma unroll
    for (int j = 0; j < 4; j++) {
        const int gc = n0 + nw + j * 8 + col;
        const float cA = addc ? Cs[nw + j * 8 + col]     : 0.f;
        const float cB = addc ? Cs[nw + j * 8 + col + 1] : 0.f;
        red_v2(out + (size_t)gr0 * K_ + gc,       acc[j * 4 + 0] + cA, acc[j * 4 + 1] + cB);
        red_v2(out + (size_t)(gr0 + 8) * K_ + gc, acc[j * 4 + 2] + cA, acc[j * 4 + 3] + cB);
    }
}

// ---------------------------------------------------------------------------
extern "C" void kernel_launch(void* const* d_in, const int* in_sizes, int n_in,
                              void* d_out, int out_size) {
    const float* x     = (const float*)d_in[0];
    const float* means = (const float*)d_in[1];
    const float* rho   = (const float*)d_in[2];
    float* out = (float*)d_out;

    cudaFuncSetAttribute(gemm_kernel, cudaFuncAttributeMaxDynamicSharedMemorySize,
                         NSTAGE * STAGE_BYTES);

    prep_kernel<<<NB_U + NB_V + NB_Z, 256>>>(x, means, rho, out);
    gemm_kernel<<<dim3(B_ / BM, K_ / BN, KSPLIT), 256, NSTAGE * STAGE_BYTES>>>(out);
}